// round 8
// baseline (speedup 1.0000x reference)
#include <cuda_runtime.h>
#include <cuda_bf16.h>

// TransientCombNoise: B=32, T=2000, BLOCK=64, MAX_DELAY=480, SR=16000.
// Per row r of N=64000, params (p0..p3):
//   att   = max(16000*(0.0005 + p0*0.0495), 1)   (always >= 8)
//   energy= p1 ; tilt = 2*p2 - 1
//   delay = int(64*(0.5 + 0.5*(0.05 + 0.95*p3)))  in [33, 63]
//   y[i]  = env(i)*energy*( noise[i] + tilt*exp(delay/att)*noise[i-delay] )
//   out   = y * rsqrt(mean(y^2) + 1e-5)
//
// ILP-2 version: each thread carries the same lane-slot of TWO independent
// rows (r and r+32000), interleaving two dependency chains so load latency
// of one chain is hidden by issue of the other. 16 lanes per row, float4
// per lane, 4-step shfl.bfly reduction per row (both rows share the group).

#define N_ROWS   (32 * 2000)
#define HALF     (N_ROWS / 2)
#define LOG2E    1.4426950408889634f

struct RowCtx {
    float a2, energy, tf_tilt;  // tf_tilt = tilt (tap exp applied later)
    int   delay;
};

__device__ __forceinline__ void row_params(const float4 p, float& a2,
                                           float& energy, float& tilt, int& delay)
{
    const float att = fmaxf(__fmul_rn(16000.0f,
                            __fadd_rn(0.0005f, __fmul_rn(p.x, 0.0495f))), 1.0f);
    energy = p.y;
    tilt   = __fmaf_rn(p.z, 2.0f, -1.0f);
    const float bw = __fadd_rn(0.05f, __fmul_rn(p.w, 0.95f));
    delay = (int)__fmul_rn(64.0f, __fadd_rn(0.5f, __fmul_rn(0.5f, bw)));
    delay = min(max(delay, 1), 480);            // effectively [33, 63]
    float inv_att;
    asm("rcp.approx.f32 %0, %1;" : "=f"(inv_att) : "f"(att));
    a2 = -LOG2E * inv_att;                       // exp(-k/att) = ex2(k*a2)
}

__device__ __forceinline__ void row_compute(
    const float4 n, const float* __restrict__ noise, int base, int i0,
    float a2, float energy, float tilt, int delay,
    float& y0, float& y1, float& y2, float& y3)
{
    float r, e0, etap;
    asm("ex2.approx.f32 %0, %1;" : "=f"(r)    : "f"(a2));
    asm("ex2.approx.f32 %0, %1;" : "=f"(e0)   : "f"((float)i0 * a2));
    asm("ex2.approx.f32 %0, %1;" : "=f"(etap) : "f"(-(float)delay * a2));
    e0 *= energy;
    const float e1 = e0 * r, e2 = e1 * r, e3 = e2 * r;
    const float tf = tilt * etap;                // <= |tilt|*e^7.9, no overflow

    const int    j  = i0 - delay;
    const float* np = noise + (base - delay);    // L1 hits (same 256B row)
    const float m0 = (j + 0 >= 0) ? np[0] : 0.0f;
    const float m1 = (j + 1 >= 0) ? np[1] : 0.0f;
    const float m2 = (j + 2 >= 0) ? np[2] : 0.0f;
    const float m3 = (j + 3 >= 0) ? np[3] : 0.0f;

    y0 = e0 * __fmaf_rn(tf, m0, n.x);
    y1 = e1 * __fmaf_rn(tf, m1, n.y);
    y2 = e2 * __fmaf_rn(tf, m2, n.z);
    y3 = e3 * __fmaf_rn(tf, m3, n.w);
}

__global__ __launch_bounds__(256) void tcn_kernel(
    const float4* __restrict__ params,  // [N_ROWS] float4
    const float*  __restrict__ noise,   // [N_ROWS, 64]
    float*        __restrict__ out)     // [N_ROWS, 64]
{
    const int tid  = blockIdx.x * 256 + threadIdx.x;
    const int pr   = tid >> 4;          // row-pair id in [0, HALF)
    const int l    = tid & 15;
    const int i0   = l << 2;

    const int rowA = pr;
    const int rowB = pr + HALF;
    const int baseA = rowA * 64 + i0;
    const int baseB = rowB * 64 + i0;

    // Issue all four independent loads up front (MLP = 4).
    const float4 pA = __ldg(params + rowA);
    const float4 pB = __ldg(params + rowB);
    const float4 nA = *reinterpret_cast<const float4*>(noise + baseA);
    const float4 nB = *reinterpret_cast<const float4*>(noise + baseB);

    float a2A, enA, tiA; int dA;
    float a2B, enB, tiB; int dB;
    row_params(pA, a2A, enA, tiA, dA);
    row_params(pB, a2B, enB, tiB, dB);

    float a0, a1, a2v, a3, b0, b1, b2, b3;
    row_compute(nA, noise, baseA, i0, a2A, enA, tiA, dA, a0, a1, a2v, a3);
    row_compute(nB, noise, baseB, i0, a2B, enB, tiB, dB, b0, b1, b2, b3);

    // Two independent 16-lane reductions, interleaved.
    float ssA = a0 * a0 + a1 * a1 + a2v * a2v + a3 * a3;
    float ssB = b0 * b0 + b1 * b1 + b2  * b2  + b3 * b3;
    #pragma unroll
    for (int o = 8; o > 0; o >>= 1) {
        ssA += __shfl_xor_sync(0xFFFFFFFFu, ssA, o);
        ssB += __shfl_xor_sync(0xFFFFFFFFu, ssB, o);
    }

    const float irA = rsqrtf(ssA * (1.0f / 64.0f) + 1e-5f);
    const float irB = rsqrtf(ssB * (1.0f / 64.0f) + 1e-5f);

    float4 oA, oB;
    oA.x = a0 * irA;  oA.y = a1 * irA;  oA.z = a2v * irA;  oA.w = a3 * irA;
    oB.x = b0 * irB;  oB.y = b1 * irB;  oB.z = b2  * irB;  oB.w = b3 * irB;
    *reinterpret_cast<float4*>(out + baseA) = oA;
    *reinterpret_cast<float4*>(out + baseB) = oB;
}

extern "C" void kernel_launch(void* const* d_in, const int* in_sizes, int n_in,
                              void* d_out, int out_size)
{
    const float4* params = (const float4*)d_in[0];  // [32,2000,4]
    const float*  noise  = (const float*)d_in[1];   // [32,2000,64]
    float* out = (float*)d_out;                     // [32, 2000*64]

    // 32000 row-pairs * 16 lanes / 256 threads = 2000 blocks (exact).
    tcn_kernel<<<(HALF * 16) / 256, 256>>>(params, noise, out);
}

// round 9
// speedup vs baseline: 1.0209x; 1.0209x over previous
#include <cuda_runtime.h>
#include <cuda_bf16.h>

// TransientCombNoise: B=32, T=2000, BLOCK=64, MAX_DELAY=480, SR=16000.
// Per row r of N=64000, params (p0..p3):
//   att   = max(16000*(0.0005 + p0*0.0495), 1)   (>= 8)
//   energy= p1 ; tilt = 2*p2 - 1
//   delay = int(64*(0.5 + 0.5*(0.05 + 0.95*p3)))  in [33, 63]
//   y[i]  = env(i)*energy*( n[i] + tilt*exp(delay/att)*n[i-delay] )
//   out   = y * rsqrt(mean(y^2) + 1e-5)
//
// One THREAD per row (params computed once, zero shuffles). Global I/O stays
// coalesced via a warp-local smem transpose with 16B-chunk XOR swizzle
// (chunk c of row r lives at physical slot c ^ (r&15)). Taps only reference
// indices <= 30 (delay >= 33), so y-chunks 0..7 are buffered in registers
// until the loop ends while chunks 8..15 stream to smem immediately.

#define N_ROWS 64000
#define TPB    128
#define LOG2E  1.4426950408889634f

__global__ __launch_bounds__(TPB) void tcn_kernel(
    const float4* __restrict__ params,  // [N_ROWS] float4
    const float*  __restrict__ noise,   // [N_ROWS, 64]
    float*        __restrict__ out)     // [N_ROWS, 64]
{
    __shared__ float s[TPB][64];        // 32 KB: one 64-sample row per thread
    __shared__ float s_ir[TPB];         // per-row 1/rms

    const int t     = threadIdx.x;
    const int w     = t >> 5;
    const int lane  = t & 31;
    const int rbase = blockIdx.x * TPB;
    const int l     = lane & 15;        // element-chunk lane within a row
    const int rh    = lane >> 4;        // which of the 2 rows this half-warp does

    // ---- cooperative coalesced load + swizzled transpose into smem ----
    #pragma unroll
    for (int it = 0; it < 16; ++it) {
        const int rl = w * 32 + it * 2 + rh;                 // local row
        const float4 v = *reinterpret_cast<const float4*>(
            noise + (rbase + rl) * 64 + l * 4);
        const int c = l ^ (rl & 15);
        *reinterpret_cast<float4*>(&s[rl][c * 4]) = v;
    }
    __syncwarp();

    // ---- per-thread (per-row) parameters ----
    const float4 p = __ldg(params + rbase + t);              // coalesced
    // Strict-rounded chain so the truncated delay matches JAX fp32 exactly.
    const float att    = fmaxf(__fmul_rn(16000.0f,
                         __fadd_rn(0.0005f, __fmul_rn(p.x, 0.0495f))), 1.0f);
    const float energy = p.y;
    const float tilt   = __fmaf_rn(p.z, 2.0f, -1.0f);
    const float bw     = __fadd_rn(0.05f, __fmul_rn(p.w, 0.95f));
    int d = (int)__fmul_rn(64.0f, __fadd_rn(0.5f, __fmul_rn(0.5f, bw)));
    d = min(max(d, 1), 480);                                 // in [33, 63]

    float inv_att;
    asm("rcp.approx.f32 %0, %1;" : "=f"(inv_att) : "f"(att));
    const float a2 = -LOG2E * inv_att;                       // env(i) = ex2(i*a2)
    float r1, etap;
    asm("ex2.approx.f32 %0, %1;" : "=f"(r1)   : "f"(a2));    // ratio per sample
    asm("ex2.approx.f32 %0, %1;" : "=f"(etap) : "f"(-(float)d * a2));
    const float tf = tilt * etap;                            // <= |tilt|*e^7.9

    // Envelope checkpoints every 8 samples (break the serial mul chain).
    float echk[8];
    #pragma unroll
    for (int g = 0; g < 8; ++g) {
        float e;
        asm("ex2.approx.f32 %0, %1;" : "=f"(e) : "f"((float)(g * 8) * a2));
        echk[g] = e * energy;
    }

    // ---- main per-row pass ----
    const int sw = t & 15;
    float ylow[32];                     // unscaled y for chunks 0..7 (deferred)
    float ss0 = 0.f, ss1 = 0.f, ss2 = 0.f, ss3 = 0.f;
    float e = 0.f;

    #pragma unroll
    for (int c = 0; c < 16; ++c) {
        const float4 xv = *reinterpret_cast<const float4*>(&s[t][(c ^ sw) * 4]);
        const float xs[4] = {xv.x, xv.y, xv.z, xv.w};
        float yv[4];
        #pragma unroll
        for (int k = 0; k < 4; ++k) {
            const int i = c * 4 + k;
            e = ((i & 7) == 0) ? echk[i >> 3] : e * r1;
            float tap = 0.f;
            if (i >= d) {               // tap index j = i-d in [0, 30]
                const int j = i - d;
                tap = s[t][(((j >> 2) ^ sw) << 2) + (j & 3)];
            }
            yv[k] = e * __fmaf_rn(tf, tap, xs[k]);
        }
        ss0 = __fmaf_rn(yv[0], yv[0], ss0);
        ss1 = __fmaf_rn(yv[1], yv[1], ss1);
        ss2 = __fmaf_rn(yv[2], yv[2], ss2);
        ss3 = __fmaf_rn(yv[3], yv[3], ss3);
        if (c < 8) {                    // keep: slots may still be tapped
            ylow[c * 4 + 0] = yv[0];
            ylow[c * 4 + 1] = yv[1];
            ylow[c * 4 + 2] = yv[2];
            ylow[c * 4 + 3] = yv[3];
        } else {                        // indices >= 32 are never tap sources
            float4 o = {yv[0], yv[1], yv[2], yv[3]};
            *reinterpret_cast<float4*>(&s[t][(c ^ sw) * 4]) = o;
        }
    }

    const float ss = (ss0 + ss1) + (ss2 + ss3);
    s_ir[t] = rsqrtf(ss * (1.0f / 64.0f) + 1e-5f);

    // Flush deferred chunks 0..7 (unscaled) back to smem.
    #pragma unroll
    for (int c = 0; c < 8; ++c) {
        float4 o = {ylow[c * 4 + 0], ylow[c * 4 + 1],
                    ylow[c * 4 + 2], ylow[c * 4 + 3]};
        *reinterpret_cast<float4*>(&s[t][(c ^ sw) * 4]) = o;
    }
    __syncwarp();

    // ---- cooperative coalesced store, applying each row's 1/rms ----
    #pragma unroll
    for (int it = 0; it < 16; ++it) {
        const int rl = w * 32 + it * 2 + rh;
        const int c  = l ^ (rl & 15);
        float4 v = *reinterpret_cast<const float4*>(&s[rl][c * 4]);
        const float ir = s_ir[rl];
        v.x *= ir; v.y *= ir; v.z *= ir; v.w *= ir;
        *reinterpret_cast<float4*>(out + (rbase + rl) * 64 + l * 4) = v;
    }
}

extern "C" void kernel_launch(void* const* d_in, const int* in_sizes, int n_in,
                              void* d_out, int out_size)
{
    const float4* params = (const float4*)d_in[0];  // [32,2000,4]
    const float*  noise  = (const float*)d_in[1];   // [32,2000,64]
    float* out = (float*)d_out;                     // [32, 2000*64]

    tcn_kernel<<<N_ROWS / TPB, TPB>>>(params, noise, out);  // 500 blocks
}